// round 4
// baseline (speedup 1.0000x reference)
#include <cuda_runtime.h>
#include <math.h>
#include <stdint.h>

#define Bn 512
#define Vn 5023
#define Fn 9976

typedef unsigned long long ull;

// ---------------- device scratch ----------------
__device__ float g_P[Bn][192];        // [betas(150)|pose_feature(36)] zero tail
__device__ float g_Arel[Bn][60];
__device__ int   g_yrot[Bn];
__device__ float g_Jpart[157][2272];
__device__ float g_Jfin[2272];
__device__ float g_D[(size_t)Vn * 564];   // [v][c][188] unified SD|PD, l-padded

// ---------------- helpers ----------------
#define CMP(v,i) ((i)==0?(v).x:((i)==1?(v).y:((i)==2?(v).z:(v).w)))

#define FMA2(acc, a, b) \
    asm("fma.rn.f32x2 %0, %1, %2, %0;" : "+l"(acc) : "l"(a), "l"(b))
#define PACK2(dd, f) \
    asm("mov.b64 %0, {%1, %1};" : "=l"(dd) : "r"(__float_as_uint(f)))
#define UNPK(lo, hi, a) \
    asm("mov.b64 {%0, %1}, %2;" : "=r"(lo), "=r"(hi) : "l"(a))

__device__ __forceinline__ void rodrigues3(const float* r, float* R) {
    const float e = 1e-8f;
    float a0 = r[0] + e, a1 = r[1] + e, a2 = r[2] + e;
    float angle = sqrtf(a0*a0 + a1*a1 + a2*a2);
    float inv = 1.f / angle;
    float ax = r[0]*inv, ay = r[1]*inv, az = r[2]*inv;
    float s = sinf(angle), c = cosf(angle), t = 1.f - c;
    R[0] = 1.f - t*(ay*ay + az*az);
    R[1] = -s*az + t*ax*ay;
    R[2] =  s*ay + t*ax*az;
    R[3] =  s*az + t*ax*ay;
    R[4] = 1.f - t*(ax*ax + az*az);
    R[5] = -s*ax + t*ay*az;
    R[6] = -s*ay + t*ax*az;
    R[7] =  s*ax + t*ay*az;
    R[8] = 1.f - t*(ax*ax + ay*ay);
}

// ---------------- K0: pack D = [shapedirs | posedirs^T | 0pad] ----------
__global__ void k_packD(const float* __restrict__ SD, const float* __restrict__ PD) {
    int i = blockIdx.x * 256 + threadIdx.x;
    if (i >= Vn * 3 * 188) return;
    int l = i % 188;
    int vc = i / 188;
    int c = vc % 3, v = vc / 3;
    float x = 0.f;
    if (l < 150)       x = SD[(size_t)v * 450 + c * 150 + l];
    else if (l < 186)  x = PD[(size_t)(l - 150) * (Vn * 3) + (size_t)v * 3 + c];
    g_D[i] = x;
}

// ---------------- K1a: split-K partials of Jr @ [shapedirs|template] -----
__global__ void k_jreg_partial(const float* __restrict__ SD,
                               const float* __restrict__ tmpl,
                               const float* __restrict__ Jr) {
    __shared__ float jr_s[5][33];
    int blk = blockIdx.x;
    int v0 = blk * 32;
    int nv = min(32, Vn - v0);
    if (threadIdx.x < 160) {
        int j = threadIdx.x >> 5, i = threadIdx.x & 31;
        jr_s[j][i] = (i < nv) ? Jr[j * Vn + v0 + i] : 0.f;
    }
    __syncthreads();

    float acc[2][5];
    int cc[2], ll[2]; bool va[2];
    #pragma unroll
    for (int s2 = 0; s2 < 2; s2++) {
        int col = threadIdx.x + s2 * 256;
        va[s2] = (col < 453);
        cc[s2] = col / 151; ll[s2] = col - cc[s2] * 151;
        #pragma unroll
        for (int j = 0; j < 5; j++) acc[s2][j] = 0.f;
    }
    for (int v = 0; v < nv; v++) {
        float jv[5];
        #pragma unroll
        for (int j = 0; j < 5; j++) jv[j] = jr_s[j][v];
        #pragma unroll
        for (int s2 = 0; s2 < 2; s2++) {
            if (va[s2]) {
                float d = (ll[s2] < 150)
                    ? SD[(size_t)(v0 + v) * 450 + cc[s2] * 150 + ll[s2]]
                    : tmpl[(size_t)(v0 + v) * 3 + cc[s2]];
                #pragma unroll
                for (int j = 0; j < 5; j++) acc[s2][j] = fmaf(jv[j], d, acc[s2][j]);
            }
        }
    }
    #pragma unroll
    for (int s2 = 0; s2 < 2; s2++)
        if (va[s2]) {
            int col = threadIdx.x + s2 * 256;
            #pragma unroll
            for (int j = 0; j < 5; j++) g_Jpart[blk][j * 453 + col] = acc[s2][j];
        }
}

__global__ void k_jreg_reduce() {
    int idx = blockIdx.x * blockDim.x + threadIdx.x;
    if (idx < 2265) {
        float s = 0.f;
        for (int k = 0; k < 157; k++) s += g_Jpart[k][idx];
        g_Jfin[idx] = s;
    }
}

// ---------------- K2: per-batch pose / joints / chain / A_rel / y_rot ----
__global__ void k_batch(const float* __restrict__ shp, const float* __restrict__ ex,
                        const float* __restrict__ pose, const float* __restrict__ eye) {
    int b = blockIdx.x * blockDim.x + threadIdx.x;
    if (b >= Bn) return;

    float fp[15];
    fp[0] = pose[b*6+0]; fp[1] = pose[b*6+1]; fp[2] = pose[b*6+2];
    fp[3] = 0.f; fp[4] = 0.f; fp[5] = 0.f;
    fp[6] = pose[b*6+3]; fp[7] = pose[b*6+4]; fp[8] = pose[b*6+5];
    #pragma unroll
    for (int i = 0; i < 6; i++) fp[9+i] = eye[b*6+i];

    float R[5][9];
    #pragma unroll
    for (int j = 0; j < 5; j++) rodrigues3(&fp[3*j], R[j]);

    float joints[5][3];
    #pragma unroll
    for (int j = 0; j < 5; j++)
        #pragma unroll
        for (int c = 0; c < 3; c++)
            joints[j][c] = g_Jfin[j*453 + c*151 + 150];
    for (int l = 0; l < 150; l++) {
        float beta = (l < 100) ? shp[b*100 + l] : ex[b*50 + (l - 100)];
        g_P[b][l] = beta;
        #pragma unroll
        for (int j = 0; j < 5; j++)
            #pragma unroll
            for (int c = 0; c < 3; c++)
                joints[j][c] = fmaf(beta, g_Jfin[j*453 + c*151 + l], joints[j][c]);
    }
    for (int j = 1; j < 5; j++)
        #pragma unroll
        for (int e = 0; e < 9; e++)
            g_P[b][150 + (j-1)*9 + e] = R[j][e] - ((e == 0 || e == 4 || e == 8) ? 1.f : 0.f);

    const int par[5] = {-1, 0, 1, 1, 1};
    float relJ[5][3];
    #pragma unroll
    for (int c = 0; c < 3; c++) relJ[0][c] = joints[0][c];
    for (int j = 1; j < 5; j++)
        #pragma unroll
        for (int c = 0; c < 3; c++) relJ[j][c] = joints[j][c] - joints[par[j]][c];

    float GR[5][9], Gt[5][3];
    #pragma unroll
    for (int e2 = 0; e2 < 9; e2++) GR[0][e2] = R[0][e2];
    #pragma unroll
    for (int c = 0; c < 3; c++) Gt[0][c] = relJ[0][c];
    for (int j = 1; j < 5; j++) {
        int p = par[j];
        for (int m = 0; m < 3; m++) {
            for (int n = 0; n < 3; n++)
                GR[j][m*3+n] = GR[p][m*3+0]*R[j][0*3+n] + GR[p][m*3+1]*R[j][1*3+n]
                             + GR[p][m*3+2]*R[j][2*3+n];
            Gt[j][m] = GR[p][m*3+0]*relJ[j][0] + GR[p][m*3+1]*relJ[j][1]
                     + GR[p][m*3+2]*relJ[j][2] + Gt[p][m];
        }
    }
    for (int j = 0; j < 5; j++)
        for (int m = 0; m < 3; m++) {
            float tr = Gt[j][m] - (GR[j][m*3+0]*joints[j][0] + GR[j][m*3+1]*joints[j][1]
                                 + GR[j][m*3+2]*joints[j][2]);
            g_Arel[b][j*12 + m*4 + 0] = GR[j][m*3+0];
            g_Arel[b][j*12 + m*4 + 1] = GR[j][m*3+1];
            g_Arel[b][j*12 + m*4 + 2] = GR[j][m*3+2];
            g_Arel[b][j*12 + m*4 + 3] = tr;
        }

    float r00 = R[0][0]*R[1][0] + R[0][1]*R[1][3] + R[0][2]*R[1][6];
    float r10 = R[0][3]*R[1][0] + R[0][4]*R[1][3] + R[0][5]*R[1][6];
    float r20 = R[0][6]*R[1][0] + R[0][7]*R[1][3] + R[0][8]*R[1][6];
    float sy = sqrtf(r00*r00 + r10*r10);
    float ydeg = atan2f(-r20, sy) * 57.29577951308232087f;
    int yr = (int)rintf(fminf(ydeg, 39.f));
    if (yr < 0) yr = (yr < -39) ? 78 : (39 - yr);
    g_yrot[b] = yr;
}

// ---------------- K3: fused GEMM + LBS -----------------------------------
// tile: 64 batches x 32 vertices; 256 threads; thread = 8 batches x 1 vertex
// P_s: [188][64] K-major (no swizzle: 8x16B lines, 4-way broadcast per warp)
// D streamed from g_D via LDG float4 (broadcast across the 8 bg threads)
#define P_FLOATS (188*64)
#define A_FLOATS (64*61)
#define SMEM_FLOATS (P_FLOATS + A_FLOATS + 160 + 96)

__global__ __launch_bounds__(256, 3)
void k_main(const float* __restrict__ tmpl, const float* __restrict__ W,
            float* __restrict__ out) {
    extern __shared__ float sm[];
    float* P_s = sm;
    float* A_s = sm + P_FLOATS;
    float* w_s = A_s + A_FLOATS;
    float* t_s = w_s + 160;

    const int tid = threadIdx.x;
    const int v0 = blockIdx.x * 32;
    const int b0 = blockIdx.y * 64;

    // ---- P transpose: g_P[b][l] -> P_s[l][b] via 4x4 register tiles ----
    for (int tile = tid; tile < 16*47; tile += 256) {
        int bq = tile & 15, lblk = tile >> 4;
        int bb = b0 + bq*4;
        float4 r0 = ((const float4*)g_P[bb+0])[lblk];
        float4 r1 = ((const float4*)g_P[bb+1])[lblk];
        float4 r2 = ((const float4*)g_P[bb+2])[lblk];
        float4 r3 = ((const float4*)g_P[bb+3])[lblk];
        #pragma unroll
        for (int j2 = 0; j2 < 4; j2++) {
            int l = lblk*4 + j2;
            *(float4*)(P_s + l*64 + bq*4) =
                make_float4(CMP(r0,j2), CMP(r1,j2), CMP(r2,j2), CMP(r3,j2));
        }
    }
    // ---- A, w, t ----
    for (int t = tid; t < 64*60; t += 256) {
        int r = t / 60, q = t - r*60;
        A_s[r*61 + q] = g_Arel[b0 + r][q];
    }
    if (tid < 160) {
        int vi = tid / 5, j = tid - vi*5;
        int v = v0 + vi;
        w_s[tid] = (v < Vn) ? W[(size_t)v*5 + j] : 0.f;
    }
    if (tid < 96) {
        int vi = tid / 3, c = tid - vi*3;
        int v = v0 + vi;
        t_s[tid] = (v < Vn) ? tmpl[(size_t)v*3 + c] : 0.f;
    }
    __syncthreads();

    const int bg = tid & 7;          // 8 groups x 8 batches
    const int vi = tid >> 3;         // 0..31
    const int v  = v0 + vi;
    const int vv = (v < Vn) ? v : 0; // clamp for safe D reads
    const float4* D4 = (const float4*)(g_D + (size_t)vv * 564);
    const float* Pb = P_s + bg * 8;

    ull acc[12];
    #pragma unroll
    for (int i = 0; i < 12; i++) acc[i] = 0ull;

    #pragma unroll 2
    for (int l0 = 0; l0 < 188; l0 += 4) {
        float4 d0 = __ldg(&D4[l0 >> 2]);
        float4 d1 = __ldg(&D4[47 + (l0 >> 2)]);
        float4 d2 = __ldg(&D4[94 + (l0 >> 2)]);
        #pragma unroll
        for (int j = 0; j < 4; j++) {
            ulonglong2 pa = *(const ulonglong2*)(Pb + (l0 + j) * 64);
            ulonglong2 pb = *(const ulonglong2*)(Pb + (l0 + j) * 64 + 4);
            ull dd0, dd1, dd2;
            PACK2(dd0, CMP(d0, j));
            PACK2(dd1, CMP(d1, j));
            PACK2(dd2, CMP(d2, j));
            FMA2(acc[0], pa.x, dd0); FMA2(acc[1],  pa.x, dd1); FMA2(acc[2],  pa.x, dd2);
            FMA2(acc[3], pa.y, dd0); FMA2(acc[4],  pa.y, dd1); FMA2(acc[5],  pa.y, dd2);
            FMA2(acc[6], pb.x, dd0); FMA2(acc[7],  pb.x, dd1); FMA2(acc[8],  pb.x, dd2);
            FMA2(acc[9], pb.y, dd0); FMA2(acc[10], pb.y, dd1); FMA2(acc[11], pb.y, dd2);
        }
    }

    // ---- epilogue: LBS ----
    float af[12][2];
    #pragma unroll
    for (int i = 0; i < 12; i++) {
        uint32_t lo, hi;
        UNPK(lo, hi, acc[i]);
        af[i][0] = __uint_as_float(lo);
        af[i][1] = __uint_as_float(hi);
    }
    float w0 = w_s[vi*5+0], w1 = w_s[vi*5+1], w2 = w_s[vi*5+2],
          w3 = w_s[vi*5+3], w4 = w_s[vi*5+4];
    float tx = t_s[vi*3+0], ty = t_s[vi*3+1], tz = t_s[vi*3+2];

    #pragma unroll
    for (int j = 0; j < 8; j++) {
        int q = j >> 1, h = j & 1;
        int bb = bg*8 + j;
        const float* Ar = A_s + bb*61;
        float T[12];
        #pragma unroll
        for (int r = 0; r < 12; r++)
            T[r] = fmaf(w0, Ar[r],
                   fmaf(w1, Ar[12+r],
                   fmaf(w2, Ar[24+r],
                   fmaf(w3, Ar[36+r], w4 * Ar[48+r]))));
        float vx = tx + af[q*3+0][h];
        float vy = ty + af[q*3+1][h];
        float vz = tz + af[q*3+2][h];
        float ox = fmaf(T[0], vx, fmaf(T[1], vy, fmaf(T[2],  vz, T[3])));
        float oy = fmaf(T[4], vx, fmaf(T[5], vy, fmaf(T[6],  vz, T[7])));
        float oz = fmaf(T[8], vx, fmaf(T[9], vy, fmaf(T[10], vz, T[11])));
        if (v < Vn) {
            size_t o = ((size_t)(b0 + bb) * Vn + v) * 3;
            out[o+0] = ox; out[o+1] = oy; out[o+2] = oz;
        }
    }
}

// ---------------- K4: landmarks ------------------------------------------
__global__ void k_lmk(const int* __restrict__ faces,
                      const int* __restrict__ sfi, const float* __restrict__ sbc,
                      const int* __restrict__ dfi, const float* __restrict__ dbc,
                      const int* __restrict__ ffi, const float* __restrict__ fbc,
                      float* __restrict__ out) {
    int b = blockIdx.x;
    int t = threadIdx.x;
    if (t >= 136) return;
    const size_t V3  = (size_t)Vn * 3;
    const size_t lm2 = (size_t)Bn * V3;
    const size_t lm3 = lm2 + (size_t)Bn * 68 * 3;

    int face; float w0, w1, w2; size_t ob;
    if (t < 68) {
        face = ffi[t]; w0 = fbc[t*3]; w1 = fbc[t*3+1]; w2 = fbc[t*3+2];
        ob = lm3 + ((size_t)b * 68 + t) * 3;
    } else {
        int lj = t - 68;
        if (lj < 17) {
            int q = g_yrot[b] * 17 + lj;
            face = dfi[q]; w0 = dbc[q*3]; w1 = dbc[q*3+1]; w2 = dbc[q*3+2];
        } else {
            int q = lj - 17;
            face = sfi[q]; w0 = sbc[q*3]; w1 = sbc[q*3+1]; w2 = sbc[q*3+2];
        }
        ob = lm2 + ((size_t)b * 68 + lj) * 3;
    }
    int f0 = faces[face*3+0], f1 = faces[face*3+1], f2 = faces[face*3+2];
    const float* vb = out + (size_t)b * V3;
    #pragma unroll
    for (int c = 0; c < 3; c++)
        out[ob + c] = w0 * vb[(size_t)f0*3 + c]
                    + w1 * vb[(size_t)f1*3 + c]
                    + w2 * vb[(size_t)f2*3 + c];
}

// ---------------- launch --------------------------------------------------
extern "C" void kernel_launch(void* const* d_in, const int* in_sizes, int n_in,
                              void* d_out, int out_size) {
    const float* shape   = (const float*)d_in[0];
    const float* expr    = (const float*)d_in[1];
    const float* pose    = (const float*)d_in[2];
    const float* eyep    = (const float*)d_in[3];
    const float* tmpl    = (const float*)d_in[4];
    const float* SD      = (const float*)d_in[5];
    const float* PD      = (const float*)d_in[6];
    const float* Jr      = (const float*)d_in[7];
    const float* W       = (const float*)d_in[8];
    const int*   faces   = (const int*)  d_in[9];
    const int*   sfi     = (const int*)  d_in[10];
    const float* sbc     = (const float*)d_in[11];
    const int*   dfi     = (const int*)  d_in[12];
    const float* dbc     = (const float*)d_in[13];
    const int*   ffi     = (const int*)  d_in[14];
    const float* fbc     = (const float*)d_in[15];
    float* out = (float*)d_out;

    k_packD<<<(Vn*3*188 + 255)/256, 256>>>(SD, PD);
    k_jreg_partial<<<157, 256>>>(SD, tmpl, Jr);
    k_jreg_reduce<<<9, 256>>>();
    k_batch<<<2, 256>>>(shape, expr, pose, eyep);

    const int smem_bytes = SMEM_FLOATS * 4;
    cudaFuncSetAttribute(k_main, cudaFuncAttributeMaxDynamicSharedMemorySize, smem_bytes);
    k_main<<<dim3(157, 8), 256, smem_bytes>>>(tmpl, W, out);

    k_lmk<<<Bn, 160>>>(faces, sfi, sbc, dfi, dbc, ffi, fbc, out);
}